// round 3
// baseline (speedup 1.0000x reference)
#include <cuda_runtime.h>
#include <math.h>

#define D_MODEL 1024
#define N_HEADS 16
#define HD      64
#define BATCH   2
#define SEQ     2048
#define ROWS    (BATCH*SEQ)      // 4096
#define QKV_N   (3*D_MODEL)      // 3072
#define LN_EPS  1e-6f

// Scratch (device-global: no runtime allocation allowed)
__device__ float g_qkv[(size_t)ROWS * QKV_N];   // 48 MB
__device__ float g_ctx[(size_t)ROWS * D_MODEL]; // 16 MB

// ---------------------------------------------------------------------------
// GEMM: C[M,N] = A[M,K] @ B[K,N], row-major. M%128==0, N%128==0, K%8==0.
// 128x128 block tile, BK=8, 256 threads, 8x8 per thread.
// ---------------------------------------------------------------------------
__global__ __launch_bounds__(256)
void gemm_kernel(const float* __restrict__ A, const float* __restrict__ Bm,
                 float* __restrict__ C, int M, int N, int K) {
    __shared__ float As[8][129];                  // padded: transposed A tile
    __shared__ __align__(16) float Bs[8][128];    // 16B-aligned for float4 reads

    const int tid = threadIdx.x;
    const int tx = tid & 15;          // 0..15  -> column group (8 cols each)
    const int ty = tid >> 4;          // 0..15  -> row group    (8 rows each)
    const int bm = blockIdx.y * 128;
    const int bn = blockIdx.x * 128;

    float acc[8][8];
#pragma unroll
    for (int i = 0; i < 8; i++)
#pragma unroll
        for (int j = 0; j < 8; j++) acc[i][j] = 0.f;

    for (int k0 = 0; k0 < K; k0 += 8) {
        // Load A tile 128x8 -> As[k][m]
#pragma unroll
        for (int l = 0; l < 4; l++) {
            int idx = tid + l * 256;
            int m = idx >> 3, kk = idx & 7;
            As[kk][m] = A[(size_t)(bm + m) * K + k0 + kk];
        }
        // Load B tile 8x128 -> Bs[k][n]   (fully coalesced)
#pragma unroll
        for (int l = 0; l < 4; l++) {
            int idx = tid + l * 256;
            int kk = idx >> 7, n = idx & 127;
            Bs[kk][n] = Bm[(size_t)(k0 + kk) * N + bn + n];
        }
        __syncthreads();

#pragma unroll
        for (int kk = 0; kk < 8; kk++) {
            float a[8];
#pragma unroll
            for (int i = 0; i < 8; i++) a[i] = As[kk][ty * 8 + i];
            float4 b0 = *(const float4*)&Bs[kk][tx * 8];
            float4 b1 = *(const float4*)&Bs[kk][tx * 8 + 4];
            float b[8] = {b0.x, b0.y, b0.z, b0.w, b1.x, b1.y, b1.z, b1.w};
#pragma unroll
            for (int i = 0; i < 8; i++)
#pragma unroll
                for (int j = 0; j < 8; j++)
                    acc[i][j] += a[i] * b[j];
        }
        __syncthreads();
    }

#pragma unroll
    for (int i = 0; i < 8; i++) {
        float* crow = C + (size_t)(bm + ty * 8 + i) * N + bn + tx * 8;
#pragma unroll
        for (int j = 0; j < 8; j++) crow[j] = acc[i][j];
    }
}

// ---------------------------------------------------------------------------
// LayerNorm over last dim (1024), scale-only (no bias), in-place on qkv.
// blockIdx.x = row (0..4095), blockIdx.y = 0 (q) / 1 (k). 256 threads.
// ---------------------------------------------------------------------------
__global__ __launch_bounds__(256)
void ln_kernel(float* __restrict__ qkv, const float* __restrict__ q_scale,
               const float* __restrict__ k_scale) {
    const int row = blockIdx.x;
    const int which = blockIdx.y;
    const float* scale = which ? k_scale : q_scale;
    float* ptr = qkv + (size_t)row * QKV_N + which * D_MODEL;

    const int tid = threadIdx.x;
    float v[4];
    float sum = 0.f, sq = 0.f;
#pragma unroll
    for (int i = 0; i < 4; i++) {
        v[i] = ptr[tid + i * 256];
        sum += v[i];
        sq += v[i] * v[i];
    }
#pragma unroll
    for (int o = 16; o > 0; o >>= 1) {
        sum += __shfl_xor_sync(0xffffffffu, sum, o);
        sq  += __shfl_xor_sync(0xffffffffu, sq,  o);
    }
    __shared__ float ssum[8], ssq[8];
    const int warp = tid >> 5, lane = tid & 31;
    if (lane == 0) { ssum[warp] = sum; ssq[warp] = sq; }
    __syncthreads();
    if (tid == 0) {
        float a = 0.f, b = 0.f;
#pragma unroll
        for (int w = 0; w < 8; w++) { a += ssum[w]; b += ssq[w]; }
        ssum[0] = a; ssq[0] = b;
    }
    __syncthreads();
    const float mean = ssum[0] * (1.f / D_MODEL);
    const float var  = ssq[0] * (1.f / D_MODEL) - mean * mean;
    const float inv  = rsqrtf(var + LN_EPS);
#pragma unroll
    for (int i = 0; i < 4; i++) {
        int c = tid + i * 256;
        ptr[c] = (v[i] - mean) * inv * scale[c];
    }
}

// ---------------------------------------------------------------------------
// Flash attention, causal. One CTA per (q-tile of 64, head, batch).
// 256 threads as 16x16; each thread: 4 query rows x 4 output cols.
// Dynamic smem: Qs,Ks,Vs,Ps each [64][65] floats = 66560 B.
// ---------------------------------------------------------------------------
__global__ __launch_bounds__(256)
void attn_kernel(const float* __restrict__ qkv, float* __restrict__ ctx) {
    extern __shared__ float sm[];
    float (*Qs)[65] = (float(*)[65])(sm);
    float (*Ks)[65] = (float(*)[65])(sm + 4160);
    float (*Vs)[65] = (float(*)[65])(sm + 8320);
    float (*Ps)[65] = (float(*)[65])(sm + 12480);

    const int qt = blockIdx.x;   // 0..31
    const int h  = blockIdx.y;   // 0..15
    const int b  = blockIdx.z;   // 0..1
    const int tid = threadIdx.x;
    const int tx = tid & 15, ty = tid >> 4;

    const float* qbase = qkv + (size_t)b * SEQ * QKV_N + (size_t)h * HD;

    // Load Q tile [64][64]
#pragma unroll
    for (int l = 0; l < 16; l++) {
        int idx = tid + l * 256;
        int i = idx >> 6, d = idx & 63;
        Qs[i][d] = qbase[(size_t)(qt * 64 + i) * QKV_N + d];
    }

    float m[4], lsum[4], acc[4][4];
#pragma unroll
    for (int i = 0; i < 4; i++) {
        m[i] = -1e30f; lsum[i] = 0.f;
#pragma unroll
        for (int j = 0; j < 4; j++) acc[i][j] = 0.f;
    }

    for (int kt = 0; kt <= qt; kt++) {
        __syncthreads();   // previous PV reads of Ks/Vs/Ps done
        const float* kb = qkv + (size_t)(b * SEQ + kt * 64) * QKV_N + D_MODEL + h * HD;
        const float* vb = kb + D_MODEL;
#pragma unroll
        for (int l = 0; l < 16; l++) {
            int idx = tid + l * 256;
            int j = idx >> 6, d = idx & 63;
            Ks[j][d] = kb[(size_t)j * QKV_N + d];
            Vs[j][d] = vb[(size_t)j * QKV_N + d];
        }
        __syncthreads();

        // scores s = (Q/8) K^T for 4x4 sub-tile
        float s[4][4];
#pragma unroll
        for (int i = 0; i < 4; i++)
#pragma unroll
            for (int j = 0; j < 4; j++) s[i][j] = 0.f;

        for (int d = 0; d < 64; d++) {
            float a[4], bb[4];
#pragma unroll
            for (int i = 0; i < 4; i++) a[i] = Qs[ty * 4 + i][d];
#pragma unroll
            for (int j = 0; j < 4; j++) bb[j] = Ks[tx * 4 + j][d];
#pragma unroll
            for (int i = 0; i < 4; i++)
#pragma unroll
                for (int j = 0; j < 4; j++)
                    s[i][j] += a[i] * bb[j];
        }
#pragma unroll
        for (int i = 0; i < 4; i++)
#pragma unroll
            for (int j = 0; j < 4; j++) s[i][j] *= 0.125f;

        if (kt == qt) {   // causal mask within diagonal tile
#pragma unroll
            for (int i = 0; i < 4; i++)
#pragma unroll
                for (int j = 0; j < 4; j++)
                    if (tx * 4 + j > ty * 4 + i) s[i][j] = -1e30f;
        }

        // online softmax per query row (reduce over 16 tx lanes)
#pragma unroll
        for (int i = 0; i < 4; i++) {
            float rm = fmaxf(fmaxf(s[i][0], s[i][1]), fmaxf(s[i][2], s[i][3]));
#pragma unroll
            for (int o = 8; o >= 1; o >>= 1)
                rm = fmaxf(rm, __shfl_xor_sync(0xffffffffu, rm, o));
            float newm = fmaxf(m[i], rm);
            float corr = expf(m[i] - newm);
            float rs = 0.f;
#pragma unroll
            for (int j = 0; j < 4; j++) {
                s[i][j] = expf(s[i][j] - newm);
                rs += s[i][j];
            }
#pragma unroll
            for (int o = 8; o >= 1; o >>= 1)
                rs += __shfl_xor_sync(0xffffffffu, rs, o);
            lsum[i] = lsum[i] * corr + rs;
            m[i] = newm;
#pragma unroll
            for (int j = 0; j < 4; j++) acc[i][j] *= corr;
#pragma unroll
            for (int j = 0; j < 4; j++) Ps[ty * 4 + i][tx * 4 + j] = s[i][j];
        }
        __syncthreads();

        // acc += P @ V  (cols tx*4..tx*4+3 of output head-dim)
        for (int jj = 0; jj < 64; jj++) {
            float p[4], vv[4];
#pragma unroll
            for (int i = 0; i < 4; i++) p[i] = Ps[ty * 4 + i][jj];
#pragma unroll
            for (int j = 0; j < 4; j++) vv[j] = Vs[jj][tx * 4 + j];
#pragma unroll
            for (int i = 0; i < 4; i++)
#pragma unroll
                for (int j = 0; j < 4; j++)
                    acc[i][j] += p[i] * vv[j];
        }
    }

    // epilogue: ctx[b, s, h*64 + n] = acc / l
#pragma unroll
    for (int i = 0; i < 4; i++) {
        float inv = 1.f / lsum[i];
        float* crow = ctx + (size_t)(b * SEQ + qt * 64 + ty * 4 + i) * D_MODEL
                          + h * HD + tx * 4;
#pragma unroll
        for (int j = 0; j < 4; j++) crow[j] = acc[i][j] * inv;
    }
}

// ---------------------------------------------------------------------------
extern "C" void kernel_launch(void* const* d_in, const int* in_sizes, int n_in,
                              void* d_out, int out_size) {
    const float* x     = (const float*)d_in[0];
    const float* Wqkv  = (const float*)d_in[1];
    const float* qscl  = (const float*)d_in[2];
    const float* kscl  = (const float*)d_in[3];
    const float* Wout  = (const float*)d_in[4];
    float* out = (float*)d_out;

    float *qkv = nullptr, *ctx = nullptr;
    cudaGetSymbolAddress((void**)&qkv, g_qkv);
    cudaGetSymbolAddress((void**)&ctx, g_ctx);

    // 1) qkv = x @ W_qkv   [4096,1024]@[1024,3072]
    {
        dim3 grid(QKV_N / 128, ROWS / 128);
        gemm_kernel<<<grid, 256>>>(x, Wqkv, qkv, ROWS, QKV_N, D_MODEL);
    }
    // 2) QK-LayerNorm in place
    {
        dim3 grid(ROWS, 2);
        ln_kernel<<<grid, 256>>>(qkv, qscl, kscl);
    }
    // 3) causal flash attention -> ctx
    {
        const int smem = 4 * 64 * 65 * (int)sizeof(float);   // 66560 B
        cudaFuncSetAttribute(attn_kernel,
                             cudaFuncAttributeMaxDynamicSharedMemorySize, smem);
        dim3 grid(SEQ / 64, N_HEADS, BATCH);
        attn_kernel<<<grid, 256, smem>>>(qkv, ctx);
    }
    // 4) out = ctx @ W_out  [4096,1024]@[1024,1024]
    {
        dim3 grid(D_MODEL / 128, ROWS / 128);
        gemm_kernel<<<grid, 256>>>(ctx, Wout, out, ROWS, D_MODEL, D_MODEL);
    }
}

// round 5
// speedup vs baseline: 1.2722x; 1.2722x over previous
#include <cuda_runtime.h>
#include <math.h>
#include <cstdint>

#define D_MODEL 1024
#define N_HEADS 16
#define HD      64
#define BATCH   2
#define SEQ     2048
#define ROWS    (BATCH*SEQ)      // 4096
#define QKV_N   (3*D_MODEL)      // 3072
#define LN_EPS  1e-6f

// Scratch (device-global: no runtime allocation allowed)
__device__ float g_qkv[(size_t)ROWS * QKV_N];   // 48 MB
__device__ float g_ctx[(size_t)ROWS * D_MODEL]; // 16 MB

// ===========================================================================
// 3xTF32 tensor-core GEMM: C[M,N] = A[M,K] @ B[K,N], row-major, ~fp32 accurate.
// 128x128 CTA tile, BK=16, 256 threads = 8 warps (2m x 4n), warp tile 64x32.
// Each fp32 operand split hi/lo into tf32; 3 MMAs: lo*hi + hi*lo + hi*hi.
// cp.async double-buffered smem; conflict-free strides (A:20, B:136 floats).
// ===========================================================================
#define BM 128
#define BN 128
#define BK 16
#define AS_STRIDE 20
#define BS_STRIDE 136

__device__ __forceinline__ uint32_t smem_u32(const void* p) {
    return (uint32_t)__cvta_generic_to_shared(p);
}

__device__ __forceinline__ void mma_tf32(float* d, const uint32_t* a, const uint32_t* b) {
    asm volatile(
        "mma.sync.aligned.m16n8k8.row.col.f32.tf32.tf32.f32 "
        "{%0,%1,%2,%3}, {%4,%5,%6,%7}, {%8,%9}, {%0,%1,%2,%3};\n"
        : "+f"(d[0]), "+f"(d[1]), "+f"(d[2]), "+f"(d[3])
        : "r"(a[0]), "r"(a[1]), "r"(a[2]), "r"(a[3]), "r"(b[0]), "r"(b[1]));
}

// fp32 -> (tf32 hi, tf32 lo) with lo = rna_tf32(x - hi)
__device__ __forceinline__ void split_tf32(float x, uint32_t& hi, uint32_t& lo) {
    uint32_t h;
    asm("cvt.rna.tf32.f32 %0, %1;\n" : "=r"(h) : "f"(x));
    float resid = x - __uint_as_float(h);
    uint32_t l;
    asm("cvt.rna.tf32.f32 %0, %1;\n" : "=r"(l) : "f"(resid));
    hi = h; lo = l;
}

__global__ __launch_bounds__(256)
void gemm_tf32x3_kernel(const float* __restrict__ A, const float* __restrict__ B,
                        float* __restrict__ C, int M, int N, int K) {
    __shared__ __align__(16) float As[2][BM * AS_STRIDE];
    __shared__ __align__(16) float Bs[2][BK * BS_STRIDE];

    const int tid  = threadIdx.x;
    const int lane = tid & 31;
    const int warp = tid >> 5;
    const int warp_m = warp & 1;    // 0..1 -> 64 rows each
    const int warp_n = warp >> 1;   // 0..3 -> 32 cols each
    const int t4  = lane >> 2;      // groupID 0..7
    const int tm4 = lane & 3;       // 0..3
    const int bm = blockIdx.y * BM;
    const int bn = blockIdx.x * BN;

    float acc[4][4][4];
#pragma unroll
    for (int mt = 0; mt < 4; mt++)
#pragma unroll
        for (int nt = 0; nt < 4; nt++)
#pragma unroll
            for (int r = 0; r < 4; r++) acc[mt][nt][r] = 0.f;

    const int nk = K / BK;

    auto prefetch = [&](int buf, int kt) {
        const int k0 = kt * BK;
#pragma unroll
        for (int l = 0; l < 4; l++) {
            int c = tid + l * 256;           // 0..1023
            int m = c >> 3, kc = c & 7;
            const float* src = A + (size_t)(bm + m) * K + k0 + kc * 2;
            uint32_t dst = smem_u32(&As[buf][m * AS_STRIDE + kc * 2]);
            asm volatile("cp.async.ca.shared.global [%0], [%1], 8;\n"
                         :: "r"(dst), "l"(src));
        }
#pragma unroll
        for (int l = 0; l < 2; l++) {
            int c = tid + l * 256;           // 0..511
            int kk = c >> 5, n4 = c & 31;
            const float* src = B + (size_t)(k0 + kk) * N + bn + n4 * 4;
            uint32_t dst = smem_u32(&Bs[buf][kk * BS_STRIDE + n4 * 4]);
            asm volatile("cp.async.cg.shared.global [%0], [%1], 16;\n"
                         :: "r"(dst), "l"(src));
        }
        asm volatile("cp.async.commit_group;\n");
    };

    prefetch(0, 0);

    for (int kt = 0; kt < nk; kt++) {
        const int buf = kt & 1;
        if (kt + 1 < nk) {
            prefetch(buf ^ 1, kt + 1);
            asm volatile("cp.async.wait_group 1;\n");
        } else {
            asm volatile("cp.async.wait_group 0;\n");
        }
        __syncthreads();

        const float* ab = &As[buf][0];
        const float* bb = &Bs[buf][0];
#pragma unroll
        for (int ks = 0; ks < 2; ks++) {
            const int k0 = ks * 8;
            uint32_t ah[4][4], al[4][4];
#pragma unroll
            for (int mt = 0; mt < 4; mt++) {
                const int rb = warp_m * 64 + mt * 16;
                float v0 = ab[(rb + t4)     * AS_STRIDE + k0 + tm4];
                float v1 = ab[(rb + 8 + t4) * AS_STRIDE + k0 + tm4];
                float v2 = ab[(rb + t4)     * AS_STRIDE + k0 + tm4 + 4];
                float v3 = ab[(rb + 8 + t4) * AS_STRIDE + k0 + tm4 + 4];
                split_tf32(v0, ah[mt][0], al[mt][0]);
                split_tf32(v1, ah[mt][1], al[mt][1]);
                split_tf32(v2, ah[mt][2], al[mt][2]);
                split_tf32(v3, ah[mt][3], al[mt][3]);
            }
            uint32_t bh[4][2], bl[4][2];
#pragma unroll
            for (int nt = 0; nt < 4; nt++) {
                const int nb = warp_n * 32 + nt * 8;
                float v0 = bb[(k0 + tm4)     * BS_STRIDE + nb + t4];
                float v1 = bb[(k0 + tm4 + 4) * BS_STRIDE + nb + t4];
                split_tf32(v0, bh[nt][0], bl[nt][0]);
                split_tf32(v1, bh[nt][1], bl[nt][1]);
            }
#pragma unroll
            for (int mt = 0; mt < 4; mt++)
#pragma unroll
                for (int nt = 0; nt < 4; nt++) {
                    mma_tf32(acc[mt][nt], al[mt], bh[nt]);   // lo_a * hi_b
                    mma_tf32(acc[mt][nt], ah[mt], bl[nt]);   // hi_a * lo_b
                    mma_tf32(acc[mt][nt], ah[mt], bh[nt]);   // hi_a * hi_b
                }
        }
        __syncthreads();
    }

#pragma unroll
    for (int mt = 0; mt < 4; mt++) {
#pragma unroll
        for (int nt = 0; nt < 4; nt++) {
            const int row = bm + warp_m * 64 + mt * 16 + t4;
            const int col = bn + warp_n * 32 + nt * 8 + tm4 * 2;
            float2 v0 = make_float2(acc[mt][nt][0], acc[mt][nt][1]);
            float2 v1 = make_float2(acc[mt][nt][2], acc[mt][nt][3]);
            *(float2*)&C[(size_t)row * N + col]       = v0;
            *(float2*)&C[(size_t)(row + 8) * N + col] = v1;
        }
    }
}

// ---------------------------------------------------------------------------
// LayerNorm over last dim (1024), scale-only, in-place on q/k slices of qkv.
// ---------------------------------------------------------------------------
__global__ __launch_bounds__(256)
void ln_kernel(float* __restrict__ qkv, const float* __restrict__ q_scale,
               const float* __restrict__ k_scale) {
    const int row = blockIdx.x;
    const int which = blockIdx.y;
    const float* scale = which ? k_scale : q_scale;
    float* ptr = qkv + (size_t)row * QKV_N + which * D_MODEL;

    const int tid = threadIdx.x;
    float v[4];
    float sum = 0.f, sq = 0.f;
#pragma unroll
    for (int i = 0; i < 4; i++) {
        v[i] = ptr[tid + i * 256];
        sum += v[i];
        sq += v[i] * v[i];
    }
#pragma unroll
    for (int o = 16; o > 0; o >>= 1) {
        sum += __shfl_xor_sync(0xffffffffu, sum, o);
        sq  += __shfl_xor_sync(0xffffffffu, sq,  o);
    }
    __shared__ float ssum[8], ssq[8];
    const int warp = tid >> 5, lane = tid & 31;
    if (lane == 0) { ssum[warp] = sum; ssq[warp] = sq; }
    __syncthreads();
    if (tid == 0) {
        float a = 0.f, b = 0.f;
#pragma unroll
        for (int w = 0; w < 8; w++) { a += ssum[w]; b += ssq[w]; }
        ssum[0] = a; ssq[0] = b;
    }
    __syncthreads();
    const float mean = ssum[0] * (1.f / D_MODEL);
    const float var  = ssq[0] * (1.f / D_MODEL) - mean * mean;
    const float inv  = rsqrtf(var + LN_EPS);
#pragma unroll
    for (int i = 0; i < 4; i++) {
        int c = tid + i * 256;
        ptr[c] = (v[i] - mean) * inv * scale[c];
    }
}

// ---------------------------------------------------------------------------
// Flash attention, causal. One CTA per (q-tile of 64, head, batch). fp32 SIMT.
// ---------------------------------------------------------------------------
__global__ __launch_bounds__(256)
void attn_kernel(const float* __restrict__ qkv, float* __restrict__ ctx) {
    extern __shared__ float sm[];
    float (*Qs)[65] = (float(*)[65])(sm);
    float (*Ks)[65] = (float(*)[65])(sm + 4160);
    float (*Vs)[65] = (float(*)[65])(sm + 8320);
    float (*Ps)[65] = (float(*)[65])(sm + 12480);

    const int qt = blockIdx.x;
    const int h  = blockIdx.y;
    const int b  = blockIdx.z;
    const int tid = threadIdx.x;
    const int tx = tid & 15, ty = tid >> 4;

    const float* qbase = qkv + (size_t)b * SEQ * QKV_N + (size_t)h * HD;

#pragma unroll
    for (int l = 0; l < 16; l++) {
        int idx = tid + l * 256;
        int i = idx >> 6, d = idx & 63;
        Qs[i][d] = qbase[(size_t)(qt * 64 + i) * QKV_N + d];
    }

    float m[4], lsum[4], acc[4][4];
#pragma unroll
    for (int i = 0; i < 4; i++) {
        m[i] = -1e30f; lsum[i] = 0.f;
#pragma unroll
        for (int j = 0; j < 4; j++) acc[i][j] = 0.f;
    }

    for (int kt = 0; kt <= qt; kt++) {
        __syncthreads();
        const float* kb = qkv + (size_t)(b * SEQ + kt * 64) * QKV_N + D_MODEL + h * HD;
        const float* vb = kb + D_MODEL;
#pragma unroll
        for (int l = 0; l < 16; l++) {
            int idx = tid + l * 256;
            int j = idx >> 6, d = idx & 63;
            Ks[j][d] = kb[(size_t)j * QKV_N + d];
            Vs[j][d] = vb[(size_t)j * QKV_N + d];
        }
        __syncthreads();

        float s[4][4];
#pragma unroll
        for (int i = 0; i < 4; i++)
#pragma unroll
            for (int j = 0; j < 4; j++) s[i][j] = 0.f;

        for (int d = 0; d < 64; d++) {
            float a[4], bb[4];
#pragma unroll
            for (int i = 0; i < 4; i++) a[i] = Qs[ty * 4 + i][d];
#pragma unroll
            for (int j = 0; j < 4; j++) bb[j] = Ks[tx * 4 + j][d];
#pragma unroll
            for (int i = 0; i < 4; i++)
#pragma unroll
                for (int j = 0; j < 4; j++)
                    s[i][j] += a[i] * bb[j];
        }
#pragma unroll
        for (int i = 0; i < 4; i++)
#pragma unroll
            for (int j = 0; j < 4; j++) s[i][j] *= 0.125f;

        if (kt == qt) {
#pragma unroll
            for (int i = 0; i < 4; i++)
#pragma unroll
                for (int j = 0; j < 4; j++)
                    if (tx * 4 + j > ty * 4 + i) s[i][j] = -1e30f;
        }

#pragma unroll
        for (int i = 0; i < 4; i++) {
            float rm = fmaxf(fmaxf(s[i][0], s[i][1]), fmaxf(s[i][2], s[i][3]));
#pragma unroll
            for (int o = 8; o >= 1; o >>= 1)
                rm = fmaxf(rm, __shfl_xor_sync(0xffffffffu, rm, o));
            float newm = fmaxf(m[i], rm);
            float corr = expf(m[i] - newm);
            float rs = 0.f;
#pragma unroll
            for (int j = 0; j < 4; j++) {
                s[i][j] = expf(s[i][j] - newm);
                rs += s[i][j];
            }
#pragma unroll
            for (int o = 8; o >= 1; o >>= 1)
                rs += __shfl_xor_sync(0xffffffffu, rs, o);
            lsum[i] = lsum[i] * corr + rs;
            m[i] = newm;
#pragma unroll
            for (int j = 0; j < 4; j++) acc[i][j] *= corr;
#pragma unroll
            for (int j = 0; j < 4; j++) Ps[ty * 4 + i][tx * 4 + j] = s[i][j];
        }
        __syncthreads();

        for (int jj = 0; jj < 64; jj++) {
            float p[4], vv[4];
#pragma unroll
            for (int i = 0; i < 4; i++) p[i] = Ps[ty * 4 + i][jj];
#pragma unroll
            for (int j = 0; j < 4; j++) vv[j] = Vs[jj][tx * 4 + j];
#pragma unroll
            for (int i = 0; i < 4; i++)
#pragma unroll
                for (int j = 0; j < 4; j++)
                    acc[i][j] += p[i] * vv[j];
        }
    }

#pragma unroll
    for (int i = 0; i < 4; i++) {
        float inv = 1.f / lsum[i];
        float* crow = ctx + (size_t)(b * SEQ + qt * 64 + ty * 4 + i) * D_MODEL
                          + h * HD + tx * 4;
#pragma unroll
        for (int j = 0; j < 4; j++) crow[j] = acc[i][j] * inv;
    }
}

// ---------------------------------------------------------------------------
extern "C" void kernel_launch(void* const* d_in, const int* in_sizes, int n_in,
                              void* d_out, int out_size) {
    const float* x     = (const float*)d_in[0];
    const float* Wqkv  = (const float*)d_in[1];
    const float* qscl  = (const float*)d_in[2];
    const float* kscl  = (const float*)d_in[3];
    const float* Wout  = (const float*)d_in[4];
    float* out = (float*)d_out;

    float *qkv = nullptr, *ctx = nullptr;
    cudaGetSymbolAddress((void**)&qkv, g_qkv);
    cudaGetSymbolAddress((void**)&ctx, g_ctx);

    // 1) qkv = x @ W_qkv   [4096,1024]@[1024,3072]  (3xTF32 tensor cores)
    {
        dim3 grid(QKV_N / BN, ROWS / BM);
        gemm_tf32x3_kernel<<<grid, 256>>>(x, Wqkv, qkv, ROWS, QKV_N, D_MODEL);
    }
    // 2) QK-LayerNorm in place
    {
        dim3 grid(ROWS, 2);
        ln_kernel<<<grid, 256>>>(qkv, qscl, kscl);
    }
    // 3) causal flash attention -> ctx
    {
        const int smem = 4 * 64 * 65 * (int)sizeof(float);   // 66560 B
        cudaFuncSetAttribute(attn_kernel,
                             cudaFuncAttributeMaxDynamicSharedMemorySize, smem);
        dim3 grid(SEQ / 64, N_HEADS, BATCH);
        attn_kernel<<<grid, 256, smem>>>(qkv, ctx);
    }
    // 4) out = ctx @ W_out  [4096,1024]@[1024,1024]  (3xTF32 tensor cores)
    {
        dim3 grid(D_MODEL / BN, ROWS / BM);
        gemm_tf32x3_kernel<<<grid, 256>>>(ctx, Wout, out, ROWS, D_MODEL, D_MODEL);
    }
}

// round 7
// speedup vs baseline: 1.4406x; 1.1324x over previous
#include <cuda_runtime.h>
#include <math.h>
#include <cstdint>

#define D_MODEL 1024
#define N_HEADS 16
#define HD      64
#define BATCH   2
#define SEQ     2048
#define ROWS    (BATCH*SEQ)      // 4096
#define QKV_N   (3*D_MODEL)      // 3072
#define LN_EPS  1e-6f

// Scratch (device-global: no runtime allocation allowed)
__device__ float g_qkv[(size_t)ROWS * QKV_N];   // 48 MB
__device__ float g_ctx[(size_t)ROWS * D_MODEL]; // 16 MB

__device__ __forceinline__ uint32_t smem_u32(const void* p) {
    return (uint32_t)__cvta_generic_to_shared(p);
}

__device__ __forceinline__ void mma_tf32(float* d, const uint32_t* a, const uint32_t* b) {
    asm volatile(
        "mma.sync.aligned.m16n8k8.row.col.f32.tf32.tf32.f32 "
        "{%0,%1,%2,%3}, {%4,%5,%6,%7}, {%8,%9}, {%0,%1,%2,%3};\n"
        : "+f"(d[0]), "+f"(d[1]), "+f"(d[2]), "+f"(d[3])
        : "r"(a[0]), "r"(a[1]), "r"(a[2]), "r"(a[3]), "r"(b[0]), "r"(b[1]));
}

// fp32 -> (tf32 hi, tf32 lo) with lo = rna_tf32(x - hi)
__device__ __forceinline__ void split_tf32(float x, uint32_t& hi, uint32_t& lo) {
    uint32_t h;
    asm("cvt.rna.tf32.f32 %0, %1;\n" : "=r"(h) : "f"(x));
    float resid = x - __uint_as_float(h);
    uint32_t l;
    asm("cvt.rna.tf32.f32 %0, %1;\n" : "=r"(l) : "f"(resid));
    hi = h; lo = l;
}

// ===========================================================================
// 3xTF32 tensor-core GEMM (validated R4): C = A @ B, row-major.
// ===========================================================================
#define BM 128
#define BN 128
#define BK 16
#define AS_STRIDE 20
#define BS_STRIDE 136

__global__ __launch_bounds__(256)
void gemm_tf32x3_kernel(const float* __restrict__ A, const float* __restrict__ B,
                        float* __restrict__ C, int M, int N, int K) {
    __shared__ __align__(16) float As[2][BM * AS_STRIDE];
    __shared__ __align__(16) float Bs[2][BK * BS_STRIDE];

    const int tid  = threadIdx.x;
    const int lane = tid & 31;
    const int warp = tid >> 5;
    const int warp_m = warp & 1;
    const int warp_n = warp >> 1;
    const int t4  = lane >> 2;
    const int tm4 = lane & 3;
    const int bm = blockIdx.y * BM;
    const int bn = blockIdx.x * BN;

    float acc[4][4][4];
#pragma unroll
    for (int mt = 0; mt < 4; mt++)
#pragma unroll
        for (int nt = 0; nt < 4; nt++)
#pragma unroll
            for (int r = 0; r < 4; r++) acc[mt][nt][r] = 0.f;

    const int nk = K / BK;

    auto prefetch = [&](int buf, int kt) {
        const int k0 = kt * BK;
#pragma unroll
        for (int l = 0; l < 4; l++) {
            int c = tid + l * 256;
            int m = c >> 3, kc = c & 7;
            const float* src = A + (size_t)(bm + m) * K + k0 + kc * 2;
            uint32_t dst = smem_u32(&As[buf][m * AS_STRIDE + kc * 2]);
            asm volatile("cp.async.ca.shared.global [%0], [%1], 8;\n"
                         :: "r"(dst), "l"(src));
        }
#pragma unroll
        for (int l = 0; l < 2; l++) {
            int c = tid + l * 256;
            int kk = c >> 5, n4 = c & 31;
            const float* src = B + (size_t)(k0 + kk) * N + bn + n4 * 4;
            uint32_t dst = smem_u32(&Bs[buf][kk * BS_STRIDE + n4 * 4]);
            asm volatile("cp.async.cg.shared.global [%0], [%1], 16;\n"
                         :: "r"(dst), "l"(src));
        }
        asm volatile("cp.async.commit_group;\n");
    };

    prefetch(0, 0);

    for (int kt = 0; kt < nk; kt++) {
        const int buf = kt & 1;
        if (kt + 1 < nk) {
            prefetch(buf ^ 1, kt + 1);
            asm volatile("cp.async.wait_group 1;\n");
        } else {
            asm volatile("cp.async.wait_group 0;\n");
        }
        __syncthreads();

        const float* ab = &As[buf][0];
        const float* bb = &Bs[buf][0];
#pragma unroll
        for (int ks = 0; ks < 2; ks++) {
            const int k0 = ks * 8;
            uint32_t ah[4][4], al[4][4];
#pragma unroll
            for (int mt = 0; mt < 4; mt++) {
                const int rb = warp_m * 64 + mt * 16;
                float v0 = ab[(rb + t4)     * AS_STRIDE + k0 + tm4];
                float v1 = ab[(rb + 8 + t4) * AS_STRIDE + k0 + tm4];
                float v2 = ab[(rb + t4)     * AS_STRIDE + k0 + tm4 + 4];
                float v3 = ab[(rb + 8 + t4) * AS_STRIDE + k0 + tm4 + 4];
                split_tf32(v0, ah[mt][0], al[mt][0]);
                split_tf32(v1, ah[mt][1], al[mt][1]);
                split_tf32(v2, ah[mt][2], al[mt][2]);
                split_tf32(v3, ah[mt][3], al[mt][3]);
            }
            uint32_t bh[4][2], bl[4][2];
#pragma unroll
            for (int nt = 0; nt < 4; nt++) {
                const int nb = warp_n * 32 + nt * 8;
                float v0 = bb[(k0 + tm4)     * BS_STRIDE + nb + t4];
                float v1 = bb[(k0 + tm4 + 4) * BS_STRIDE + nb + t4];
                split_tf32(v0, bh[nt][0], bl[nt][0]);
                split_tf32(v1, bh[nt][1], bl[nt][1]);
            }
#pragma unroll
            for (int mt = 0; mt < 4; mt++)
#pragma unroll
                for (int nt = 0; nt < 4; nt++) {
                    mma_tf32(acc[mt][nt], al[mt], bh[nt]);
                    mma_tf32(acc[mt][nt], ah[mt], bl[nt]);
                    mma_tf32(acc[mt][nt], ah[mt], bh[nt]);
                }
        }
        __syncthreads();
    }

#pragma unroll
    for (int mt = 0; mt < 4; mt++) {
#pragma unroll
        for (int nt = 0; nt < 4; nt++) {
            const int row = bm + warp_m * 64 + mt * 16 + t4;
            const int col = bn + warp_n * 32 + nt * 8 + tm4 * 2;
            float2 v0 = make_float2(acc[mt][nt][0], acc[mt][nt][1]);
            float2 v1 = make_float2(acc[mt][nt][2], acc[mt][nt][3]);
            *(float2*)&C[(size_t)row * N + col]       = v0;
            *(float2*)&C[(size_t)(row + 8) * N + col] = v1;
        }
    }
}

// ---------------------------------------------------------------------------
// LayerNorm over last dim (1024), scale-only, in-place on q/k slices of qkv.
// ---------------------------------------------------------------------------
__global__ __launch_bounds__(256)
void ln_kernel(float* __restrict__ qkv, const float* __restrict__ q_scale,
               const float* __restrict__ k_scale) {
    const int row = blockIdx.x;
    const int which = blockIdx.y;
    const float* scale = which ? k_scale : q_scale;
    float* ptr = qkv + (size_t)row * QKV_N + which * D_MODEL;

    const int tid = threadIdx.x;
    float v[4];
    float sum = 0.f, sq = 0.f;
#pragma unroll
    for (int i = 0; i < 4; i++) {
        v[i] = ptr[tid + i * 256];
        sum += v[i];
        sq += v[i] * v[i];
    }
#pragma unroll
    for (int o = 16; o > 0; o >>= 1) {
        sum += __shfl_xor_sync(0xffffffffu, sum, o);
        sq  += __shfl_xor_sync(0xffffffffu, sq,  o);
    }
    __shared__ float ssum[8], ssq[8];
    const int warp = tid >> 5, lane = tid & 31;
    if (lane == 0) { ssum[warp] = sum; ssq[warp] = sq; }
    __syncthreads();
    if (tid == 0) {
        float a = 0.f, b = 0.f;
#pragma unroll
        for (int w = 0; w < 8; w++) { a += ssum[w]; b += ssq[w]; }
        ssum[0] = a; ssq[0] = b;
    }
    __syncthreads();
    const float mean = ssum[0] * (1.f / D_MODEL);
    const float var  = ssq[0] * (1.f / D_MODEL) - mean * mean;
    const float inv  = rsqrtf(var + LN_EPS);
#pragma unroll
    for (int i = 0; i < 4; i++) {
        int c = tid + i * 256;
        ptr[c] = (v[i] - mean) * inv * scale[c];
    }
}

// ===========================================================================
// Flash attention with 3xTF32 tensor cores. Causal.
// CTA: 64-q-row tile x (head, batch). 128 threads = 4 warps; warp owns 16 q
// rows x all 64 k cols. Q split hi/lo held in registers; K/V cp.async
// double-buffered; P via smem (reuses Q buffer). Softmax fp32 exact.
// Smem strides: Q/P/K rows 68 floats (4*t4+tm4 bank-clean),
//               V rows 72 floats (8*tm4+t4 bank-clean for transposed reads).
// ===========================================================================
#define QP_STR 68
#define K_STR  68
#define V_STR  72
// floats: QPs 64*68=4352 | Ks 2*64*68=8704 | Vs 2*64*72=9216  -> 22272 (89088 B)
#define ATTN_SMEM_FLOATS 22272

__global__ __launch_bounds__(128)
void attn_mma_kernel(const float* __restrict__ qkv, float* __restrict__ ctx) {
    extern __shared__ float sm[];
    float* QPs = sm;                 // Q tile, later P tile
    float* Ksm = sm + 4352;          // 2 buffers of 64*68
    float* Vsm = sm + 13056;         // 2 buffers of 64*72

    const int qt = blockIdx.x;       // 0..31
    const int h  = blockIdx.y;
    const int b  = blockIdx.z;
    const int tid  = threadIdx.x;
    const int lane = tid & 31;
    const int w    = tid >> 5;       // warp 0..3 -> q rows w*16..w*16+15
    const int t4   = lane >> 2;      // 0..7
    const int tm4  = lane & 3;       // 0..3
    const int w16  = w * 16;

    const float* qbase = qkv + ((size_t)(b * SEQ + qt * 64)) * QKV_N + (size_t)h * HD;

    auto prefetch_kv = [&](int buf, int kt) {
        const float* kb = qkv + ((size_t)(b * SEQ + kt * 64)) * QKV_N + D_MODEL + (size_t)h * HD;
        const float* vb = kb + D_MODEL;
        float* Kd = Ksm + buf * (64 * K_STR);
        float* Vd = Vsm + buf * (64 * V_STR);
#pragma unroll
        for (int l = 0; l < 8; l++) {
            int c = tid + l * 128;           // 0..1023
            int row = c >> 4, c4 = c & 15;
            const float* srcK = kb + (size_t)row * QKV_N + c4 * 4;
            uint32_t dstK = smem_u32(&Kd[row * K_STR + c4 * 4]);
            asm volatile("cp.async.cg.shared.global [%0], [%1], 16;\n"
                         :: "r"(dstK), "l"(srcK));
            const float* srcV = vb + (size_t)row * QKV_N + c4 * 4;
            uint32_t dstV = smem_u32(&Vd[row * V_STR + c4 * 4]);
            asm volatile("cp.async.cg.shared.global [%0], [%1], 16;\n"
                         :: "r"(dstV), "l"(srcV));
        }
        asm volatile("cp.async.commit_group;\n");
    };

    // start first K/V prefetch, then load Q tile (synchronous float4)
    prefetch_kv(0, 0);
#pragma unroll
    for (int l = 0; l < 8; l++) {
        int c = tid + l * 128;
        int row = c >> 4, c4 = c & 15;
        float4 v = *(const float4*)(qbase + (size_t)row * QKV_N + c4 * 4);
        *(float4*)&QPs[row * QP_STR + c4 * 4] = v;
    }
    __syncthreads();

    // Q fragments (persistent hi/lo), pre-scaled by 1/sqrt(Hd)=0.125
    uint32_t qah[8][4], qal[8][4];
#pragma unroll
    for (int ks = 0; ks < 8; ks++) {
        const int k0 = ks * 8;
        float v0 = 0.125f * QPs[(w16 + t4)     * QP_STR + k0 + tm4];
        float v1 = 0.125f * QPs[(w16 + t4 + 8) * QP_STR + k0 + tm4];
        float v2 = 0.125f * QPs[(w16 + t4)     * QP_STR + k0 + tm4 + 4];
        float v3 = 0.125f * QPs[(w16 + t4 + 8) * QP_STR + k0 + tm4 + 4];
        split_tf32(v0, qah[ks][0], qal[ks][0]);
        split_tf32(v1, qah[ks][1], qal[ks][1]);
        split_tf32(v2, qah[ks][2], qal[ks][2]);
        split_tf32(v3, qah[ks][3], qal[ks][3]);
    }
    __syncthreads();   // QPs now free -> becomes Ps

    float m0 = -1e30f, m1 = -1e30f, l0 = 0.f, l1 = 0.f;
    float oacc[8][4];
#pragma unroll
    for (int nt = 0; nt < 8; nt++)
#pragma unroll
        for (int r = 0; r < 4; r++) oacc[nt][r] = 0.f;

    for (int kt = 0; kt <= qt; kt++) {
        const int buf = kt & 1;
        asm volatile("cp.async.wait_group 0;\n");
        __syncthreads();
        if (kt < qt) prefetch_kv(buf ^ 1, kt + 1);

        const float* Kb = Ksm + buf * (64 * K_STR);
        const float* Vb = Vsm + buf * (64 * V_STR);

        // ---- scores S = (Q*0.125) @ K^T  (3xTF32) ----
        float s[8][4];
#pragma unroll
        for (int nt = 0; nt < 8; nt++)
#pragma unroll
            for (int r = 0; r < 4; r++) s[nt][r] = 0.f;

#pragma unroll
        for (int ks = 0; ks < 8; ks++) {
            const int k0 = ks * 8;
            uint32_t kh[8][2], kl[8][2];
#pragma unroll
            for (int nt = 0; nt < 8; nt++) {
                float v0 = Kb[(nt * 8 + t4) * K_STR + k0 + tm4];
                float v1 = Kb[(nt * 8 + t4) * K_STR + k0 + tm4 + 4];
                split_tf32(v0, kh[nt][0], kl[nt][0]);
                split_tf32(v1, kh[nt][1], kl[nt][1]);
            }
#pragma unroll
            for (int nt = 0; nt < 8; nt++) {
                mma_tf32(s[nt], qal[ks], kh[nt]);
                mma_tf32(s[nt], qah[ks], kl[nt]);
                mma_tf32(s[nt], qah[ks], kh[nt]);
            }
        }

        // causal mask on diagonal tile
        if (kt == qt) {
#pragma unroll
            for (int nt = 0; nt < 8; nt++) {
                const int c0 = nt * 8 + tm4 * 2;
                const int r0 = w16 + t4;
                if (c0     > r0)     s[nt][0] = -1e30f;
                if (c0 + 1 > r0)     s[nt][1] = -1e30f;
                if (c0     > r0 + 8) s[nt][2] = -1e30f;
                if (c0 + 1 > r0 + 8) s[nt][3] = -1e30f;
            }
        }

        // ---- online softmax (rows t4 / t4+8 of this warp) ----
        float rm0 = -1e30f, rm1 = -1e30f;
#pragma unroll
        for (int nt = 0; nt < 8; nt++) {
            rm0 = fmaxf(rm0, fmaxf(s[nt][0], s[nt][1]));
            rm1 = fmaxf(rm1, fmaxf(s[nt][2], s[nt][3]));
        }
#pragma unroll
        for (int o = 1; o <= 2; o <<= 1) {
            rm0 = fmaxf(rm0, __shfl_xor_sync(0xffffffffu, rm0, o));
            rm1 = fmaxf(rm1, __shfl_xor_sync(0xffffffffu, rm1, o));
        }
        const float nm0 = fmaxf(m0, rm0);
        const float nm1 = fmaxf(m1, rm1);
        const float c0 = expf(m0 - nm0);
        const float c1 = expf(m1 - nm1);
        float rs0 = 0.f, rs1 = 0.f;
#pragma unroll
        for (int nt = 0; nt < 8; nt++) {
            s[nt][0] = expf(s[nt][0] - nm0);
            s[nt][1] = expf(s[nt][1] - nm0);
            s[nt][2] = expf(s[nt][2] - nm1);
            s[nt][3] = expf(s[nt][3] - nm1);
            rs0 += s[nt][0] + s[nt][1];
            rs1 += s[nt][2] + s[nt][3];
        }
#pragma unroll
        for (int o = 1; o <= 2; o <<= 1) {
            rs0 += __shfl_xor_sync(0xffffffffu, rs0, o);
            rs1 += __shfl_xor_sync(0xffffffffu, rs1, o);
        }
        l0 = l0 * c0 + rs0;  m0 = nm0;
        l1 = l1 * c1 + rs1;  m1 = nm1;
#pragma unroll
        for (int nt = 0; nt < 8; nt++) {
            oacc[nt][0] *= c0; oacc[nt][1] *= c0;
            oacc[nt][2] *= c1; oacc[nt][3] *= c1;
        }

        // write P to smem (own warp's 16-row slice), float2 stores
#pragma unroll
        for (int nt = 0; nt < 8; nt++) {
            *(float2*)&QPs[(w16 + t4)     * QP_STR + nt * 8 + tm4 * 2] =
                make_float2(s[nt][0], s[nt][1]);
            *(float2*)&QPs[(w16 + t4 + 8) * QP_STR + nt * 8 + tm4 * 2] =
                make_float2(s[nt][2], s[nt][3]);
        }
        __syncwarp();

        // ---- O += P @ V  (3xTF32) ----
#pragma unroll
        for (int ks = 0; ks < 8; ks++) {
            const int k0 = ks * 8;
            uint32_t pah[4], pal[4];
            {
                float v0 = QPs[(w16 + t4)     * QP_STR + k0 + tm4];
                float v1 = QPs[(w16 + t4 + 8) * QP_STR + k0 + tm4];
                float v2 = QPs[(w16 + t4)     * QP_STR + k0 + tm4 + 4];
                float v3 = QPs[(w16 + t4 + 8) * QP_STR + k0 + tm4 + 4];
                split_tf32(v0, pah[0], pal[0]);
                split_tf32(v1, pah[1], pal[1]);
                split_tf32(v2, pah[2], pal[2]);
                split_tf32(v3, pah[3], pal[3]);
            }
#pragma unroll
            for (int nt = 0; nt < 8; nt++) {
                uint32_t vh[2], vl[2];
                float v0 = Vb[(k0 + tm4)     * V_STR + nt * 8 + t4];
                float v1 = Vb[(k0 + tm4 + 4) * V_STR + nt * 8 + t4];
                split_tf32(v0, vh[0], vl[0]);
                split_tf32(v1, vh[1], vl[1]);
                mma_tf32(oacc[nt], pal, vh);
                mma_tf32(oacc[nt], pah, vl);
                mma_tf32(oacc[nt], pah, vh);
            }
        }
        __syncwarp();   // done with QPs before next iteration rewrites it
    }

    // epilogue
    const float i0 = 1.f / l0, i1 = 1.f / l1;
    const size_t r0 = (size_t)(b * SEQ + qt * 64 + w16 + t4) * D_MODEL;
    const size_t r1 = (size_t)(b * SEQ + qt * 64 + w16 + t4 + 8) * D_MODEL;
#pragma unroll
    for (int nt = 0; nt < 8; nt++) {
        const int col = h * HD + nt * 8 + tm4 * 2;
        *(float2*)&ctx[r0 + col] = make_float2(oacc[nt][0] * i0, oacc[nt][1] * i0);
        *(float2*)&ctx[r1 + col] = make_float2(oacc[nt][2] * i1, oacc[nt][3] * i1);
    }
}

// ---------------------------------------------------------------------------
extern "C" void kernel_launch(void* const* d_in, const int* in_sizes, int n_in,
                              void* d_out, int out_size) {
    const float* x     = (const float*)d_in[0];
    const float* Wqkv  = (const float*)d_in[1];
    const float* qscl  = (const float*)d_in[2];
    const float* kscl  = (const float*)d_in[3];
    const float* Wout  = (const float*)d_in[4];
    float* out = (float*)d_out;

    float *qkv = nullptr, *ctx = nullptr;
    cudaGetSymbolAddress((void**)&qkv, g_qkv);
    cudaGetSymbolAddress((void**)&ctx, g_ctx);

    // 1) qkv = x @ W_qkv   (3xTF32)
    {
        dim3 grid(QKV_N / BN, ROWS / BM);
        gemm_tf32x3_kernel<<<grid, 256>>>(x, Wqkv, qkv, ROWS, QKV_N, D_MODEL);
    }
    // 2) QK-LayerNorm in place
    {
        dim3 grid(ROWS, 2);
        ln_kernel<<<grid, 256>>>(qkv, qscl, kscl);
    }
    // 3) causal flash attention (3xTF32 tensor cores) -> ctx
    {
        const int smem = ATTN_SMEM_FLOATS * (int)sizeof(float);  // 89088 B
        cudaFuncSetAttribute(attn_mma_kernel,
                             cudaFuncAttributeMaxDynamicSharedMemorySize, smem);
        dim3 grid(SEQ / 64, N_HEADS, BATCH);
        attn_mma_kernel<<<grid, 128, smem>>>(qkv, ctx);
    }
    // 4) out = ctx @ W_out  (3xTF32)
    {
        dim3 grid(D_MODEL / BN, ROWS / BM);
        gemm_tf32x3_kernel<<<grid, 256>>>(ctx, Wout, out, ROWS, D_MODEL, D_MODEL);
    }
}